// round 10
// baseline (speedup 1.0000x reference)
#include <cuda_runtime.h>
#include <cuda_fp16.h>
#include <cstdint>

#define H 128

// Scratch: segment sums [G,H]; c[g] = s[g] @ W1[128:256] + b1  (fp32).
__device__ float g_agg[4096 * 128];
__device__ float g_c[4096 * 128];

// ============================================================================
// Base-target PTX helpers
// ============================================================================
__device__ __forceinline__ uint32_t pack_f16x2(float lo, float hi) {
    uint32_t u;
    asm("cvt.rn.f16x2.f32 %0, %1, %2;" : "=r"(u) : "f"(hi), "f"(lo));
    return u;
}
__device__ __forceinline__ uint32_t smem_u32_of(const void* p) {
    uint32_t a;
    asm("{ .reg .u64 t; cvta.to.shared.u64 t, %1; cvt.u32.u64 %0, t; }"
        : "=r"(a) : "l"(p));
    return a;
}
__device__ __forceinline__ void mma16(float* d, const uint32_t* a,
                                      uint32_t b0, uint32_t b1) {
    asm volatile(
        "mma.sync.aligned.m16n8k16.row.col.f32.f16.f16.f32 "
        "{%0,%1,%2,%3},{%4,%5,%6,%7},{%8,%9},{%0,%1,%2,%3};"
        : "+f"(d[0]), "+f"(d[1]), "+f"(d[2]), "+f"(d[3])
        : "r"(a[0]), "r"(a[1]), "r"(a[2]), "r"(a[3]), "r"(b0), "r"(b1));
}
__device__ __forceinline__ void ldsm4(uint32_t& r0, uint32_t& r1,
                                      uint32_t& r2, uint32_t& r3, uint32_t addr) {
    asm volatile("ldmatrix.sync.aligned.m8n8.x4.shared.b16 {%0,%1,%2,%3}, [%4];"
                 : "=r"(r0), "=r"(r1), "=r"(r2), "=r"(r3) : "r"(addr));
}

// ============================================================================
// Small kernels (R7 chain)
// ============================================================================
__global__ void zero_agg_kernel(int n) {
    int i = blockIdx.x * blockDim.x + threadIdx.x;
    if (i < n) g_agg[i] = 0.0f;
}

__global__ void seg_sum_kernel(const float4* __restrict__ node4,
                               const int* __restrict__ seg) {
    __shared__ int sseg[512];
    const int base = blockIdx.x * 512;
    const int tid = threadIdx.x;
    for (int i = tid; i < 512; i += 256) sseg[i] = seg[base + i];
    __syncthreads();
    const int c4 = tid & 31, rp = tid >> 5;
    const int r0 = rp * 64;
    float4 acc = make_float4(0.f, 0.f, 0.f, 0.f);
    int cur = sseg[r0];
    #pragma unroll 4
    for (int i = 0; i < 64; ++i) {
        const int r = r0 + i;
        const int id = sseg[r];
        if (id != cur) {
            float* dst = &g_agg[cur * H + c4 * 4];
            atomicAdd(dst + 0, acc.x); atomicAdd(dst + 1, acc.y);
            atomicAdd(dst + 2, acc.z); atomicAdd(dst + 3, acc.w);
            acc = make_float4(0.f, 0.f, 0.f, 0.f);
            cur = id;
        }
        float4 v = node4[(size_t)(base + r) * 32 + c4];
        acc.x += v.x; acc.y += v.y; acc.z += v.z; acc.w += v.w;
    }
    float* dst = &g_agg[cur * H + c4 * 4];
    atomicAdd(dst + 0, acc.x); atomicAdd(dst + 1, acc.y);
    atomicAdd(dst + 2, acc.z); atomicAdd(dst + 3, acc.w);
}

__global__ void set_mlp_c_kernel(const float* __restrict__ uset,
                                 const float* __restrict__ Ws1,
                                 const float* __restrict__ bs1,
                                 const float* __restrict__ Ws2,
                                 const float* __restrict__ bs2,
                                 const float* __restrict__ W1g,
                                 const float* __restrict__ b1g,
                                 float* __restrict__ s_out) {
    __shared__ float x[8][256];
    __shared__ float h1[8][128];
    __shared__ float sres[8][128];
    const int j = threadIdx.x;
    const int rbase = blockIdx.x * 8;
    for (int idx = j; idx < 8 * 256; idx += 128) {
        int r = idx >> 8, k = idx & 255;
        x[r][k] = (k < 128) ? g_agg[(rbase + r) * H + k]
                            : uset[(size_t)(rbase + r) * H + (k - 128)];
    }
    __syncthreads();
    float acc[8];
    float b1 = bs1[j];
    #pragma unroll
    for (int r = 0; r < 8; ++r) acc[r] = b1;
    for (int k = 0; k < 256; ++k) {
        float w = Ws1[k * H + j];
        #pragma unroll
        for (int r = 0; r < 8; ++r) acc[r] += x[r][k] * w;
    }
    #pragma unroll
    for (int r = 0; r < 8; ++r) h1[r][j] = fmaxf(acc[r], 0.0f);
    __syncthreads();
    float b2 = bs2[j];
    #pragma unroll
    for (int r = 0; r < 8; ++r) acc[r] = b2;
    for (int k = 0; k < 128; ++k) {
        float w = Ws2[k * H + j];
        #pragma unroll
        for (int r = 0; r < 8; ++r) acc[r] += h1[r][k] * w;
    }
    #pragma unroll
    for (int r = 0; r < 8; ++r) {
        float v = fmaxf(acc[r], 0.0f);
        sres[r][j] = v;
        s_out[(size_t)(rbase + r) * H + j] = v;
    }
    __syncthreads();
    float bb = b1g[j];
    #pragma unroll
    for (int r = 0; r < 8; ++r) acc[r] = bb;
    for (int k = 0; k < 128; ++k) {
        float w = W1g[(size_t)(128 + k) * H + j];
        #pragma unroll
        for (int r = 0; r < 8; ++r) acc[r] += sres[r][k] * w;
    }
    #pragma unroll
    for (int r = 0; r < 8; ++r) g_c[(size_t)(rbase + r) * H + j] = acc[r];
}

// ============================================================================
// Fused node MLP: 256 threads/block, 2 blocks/SM (two barrier domains),
// 64-row tiles, all-fp16 MMA, X fp32-LDG -> fp16 STS inside the kernel.
// fp16 smem: 256B/row, o = row*256 + (((k>>3)^(row&7))<<4) + (k&7)*2.
// ============================================================================
#define W1_OFF   0        // 32768
#define W2_OFF   32768    // 32768
#define X_OFF    65536    // 16384 (64 rows)
#define H1_OFF   81920    // 16384
#define B2S_OFF  98304    // 512
#define F_SMEM   98816

__global__ void __launch_bounds__(256, 2)
fused_node_mlp(const float* __restrict__ node,
               const int* __restrict__ seg,
               const float* __restrict__ W1g,
               const float* __restrict__ W2g,
               const float* __restrict__ b2g,
               float* __restrict__ n_out,
               int numTiles) {
    extern __shared__ __align__(16) char smem[];
    const uint32_t sb = smem_u32_of(smem);
    float* b2s = (float*)(smem + B2S_OFF);

    const int tid = threadIdx.x, lane = tid & 31, wid = tid >> 5;
    const int wr = wid & 1, wc = wid >> 1;      // 2 row slabs x 4 col groups
    const int gr = lane >> 2, tg = lane & 3;

    // X staging: 64 rows x 16 units(16B fp16 = 8 k each); 256 thr x 4 units
    const int xrow = tid & 63;
    const int xu0 = (tid >> 6) * 4;

    // one-time: W1a fp16, W2 fp16, bias
    for (int idx = tid; idx < 128 * 128; idx += 256) {
        int n = idx >> 7, k = idx & 127;
        uint32_t o = (uint32_t)n * 256u + ((((uint32_t)k >> 3) ^ (n & 7)) << 4)
                   + ((uint32_t)k & 7) * 2u;
        *(__half*)(smem + W1_OFF + o) = __float2half_rn(W1g[(size_t)k * H + n]);
        *(__half*)(smem + W2_OFF + o) = __float2half_rn(W2g[(size_t)k * H + n]);
    }
    if (tid < 128) b2s[tid] = b2g[tid];

    // ldsm lane constants
    const int subA = lane & 7;
    const int arow0 = wr * 32 + ((lane >> 3) & 1) * 8 + subA;   // + mt*16 (<64)
    const int hA = lane >> 4;
    const int subB = lane & 7;
    const int brow0 = wc * 32 + ((lane >> 4) & 1) * 8 + subB;   // + p*16 (<128)
    const int hB = (lane >> 3) & 1;

    float acc[2][4][4];
    float2 cpre[2][2][4];
    int sga[2][2];

    // prologue: X(tile0) LDG+cvt+STS; seg+c prefetch for tile0
    if (blockIdx.x < numTiles) {
        const int base = blockIdx.x * 64;
        #pragma unroll
        for (int i = 0; i < 4; ++i) {
            const int u = xu0 + i;
            const float* src = &node[(size_t)(base + xrow) * H + u * 8];
            float4 va = *(const float4*)src;
            float4 vb = *(const float4*)(src + 4);
            uint4 v;
            v.x = pack_f16x2(va.x, va.y); v.y = pack_f16x2(va.z, va.w);
            v.z = pack_f16x2(vb.x, vb.y); v.w = pack_f16x2(vb.z, vb.w);
            *(uint4*)(smem + X_OFF + (uint32_t)xrow * 256u
                      + ((((uint32_t)u) ^ ((uint32_t)xrow & 7)) << 4)) = v;
        }
        #pragma unroll
        for (int mt = 0; mt < 2; ++mt) {
            const int ra = base + wr * 32 + mt * 16 + gr;
            sga[mt][0] = seg[ra];
            sga[mt][1] = seg[ra + 8];
        }
        #pragma unroll
        for (int mt = 0; mt < 2; ++mt)
            #pragma unroll
            for (int nt = 0; nt < 4; ++nt) {
                const int col = wc * 32 + nt * 8 + 2 * tg;
                cpre[mt][0][nt] = *(const float2*)&g_c[(size_t)sga[mt][0] * H + col];
                cpre[mt][1][nt] = *(const float2*)&g_c[(size_t)sga[mt][1] * H + col];
            }
    }

    for (int tile = blockIdx.x; tile < numTiles; tile += gridDim.x) {
        const int base = tile * 64;
        const int nxt = tile + gridDim.x;

        __syncthreads();   // (a) X STS + weights visible; prev h1 reads done

        // acc init = c[seg] (prefetched)
        #pragma unroll
        for (int mt = 0; mt < 2; ++mt)
            #pragma unroll
            for (int nt = 0; nt < 4; ++nt) {
                acc[mt][nt][0] = cpre[mt][0][nt].x;
                acc[mt][nt][1] = cpre[mt][0][nt].y;
                acc[mt][nt][2] = cpre[mt][1][nt].x;
                acc[mt][nt][3] = cpre[mt][1][nt].y;
            }

        // seg prefetch for next tile (hidden under layer1)
        if (nxt < numTiles) {
            const int nb = nxt * 64;
            #pragma unroll
            for (int mt = 0; mt < 2; ++mt) {
                const int ra = nb + wr * 32 + mt * 16 + gr;
                sga[mt][0] = seg[ra];
                sga[mt][1] = seg[ra + 8];
            }
        }

        // ---- layer1 (fp16): X @ W1a ----
        #pragma unroll
        for (int ks = 0; ks < 8; ++ks) {
            uint32_t A[2][4], B[2][4];
            #pragma unroll
            for (int mt = 0; mt < 2; ++mt) {
                uint32_t ad = sb + X_OFF + (uint32_t)(arow0 + mt * 16) * 256u
                            + ((((ks << 1) + hA) ^ subA) << 4);
                ldsm4(A[mt][0], A[mt][1], A[mt][2], A[mt][3], ad);
            }
            #pragma unroll
            for (int p = 0; p < 2; ++p) {
                uint32_t bd = sb + W1_OFF + (uint32_t)(brow0 + p * 16) * 256u
                            + ((((ks << 1) + hB) ^ subB) << 4);
                ldsm4(B[p][0], B[p][1], B[p][2], B[p][3], bd);
            }
            #pragma unroll
            for (int mt = 0; mt < 2; ++mt) {
                mma16(acc[mt][0], A[mt], B[0][0], B[0][1]);
                mma16(acc[mt][1], A[mt], B[0][2], B[0][3]);
                mma16(acc[mt][2], A[mt], B[1][0], B[1][1]);
                mma16(acc[mt][3], A[mt], B[1][2], B[1][3]);
            }
        }

        // ---- epilogue1: relu, fp16 -> h1 ----
        #pragma unroll
        for (int mt = 0; mt < 2; ++mt) {
            const int ra = wr * 32 + mt * 16 + gr;
            #pragma unroll
            for (int nt = 0; nt < 4; ++nt) {
                const int col = wc * 32 + nt * 8 + 2 * tg;
                const uint32_t unit = (uint32_t)(col >> 3);
                uint32_t v01 = pack_f16x2(fmaxf(acc[mt][nt][0], 0.0f),
                                          fmaxf(acc[mt][nt][1], 0.0f));
                *(uint32_t*)(smem + H1_OFF + (uint32_t)ra * 256u
                             + ((unit ^ ((uint32_t)ra & 7)) << 4)
                             + ((uint32_t)col & 7) * 2u) = v01;
                uint32_t v23 = pack_f16x2(fmaxf(acc[mt][nt][2], 0.0f),
                                          fmaxf(acc[mt][nt][3], 0.0f));
                *(uint32_t*)(smem + H1_OFF + (uint32_t)(ra + 8) * 256u
                             + ((unit ^ (((uint32_t)ra + 8) & 7)) << 4)
                             + ((uint32_t)col & 7) * 2u) = v23;
                #pragma unroll
                for (int j = 0; j < 4; ++j) acc[mt][nt][j] = 0.0f;
            }
        }
        __syncthreads();   // (b) h1 visible; X buffer free (layer1 done)

        // LDG next-tile X (latency hidden under layer2 + other block)
        float4 pa[4], pb[4];
        if (nxt < numTiles) {
            const int nb = nxt * 64;
            #pragma unroll
            for (int i = 0; i < 4; ++i) {
                const int u = xu0 + i;
                const float* src = &node[(size_t)(nb + xrow) * H + u * 8];
                pa[i] = *(const float4*)src;
                pb[i] = *(const float4*)(src + 4);
            }
        }

        // c[seg] prefetch for next tile
        if (nxt < numTiles) {
            #pragma unroll
            for (int mt = 0; mt < 2; ++mt)
                #pragma unroll
                for (int nt = 0; nt < 4; ++nt) {
                    const int col = wc * 32 + nt * 8 + 2 * tg;
                    cpre[mt][0][nt] = *(const float2*)&g_c[(size_t)sga[mt][0] * H + col];
                    cpre[mt][1][nt] = *(const float2*)&g_c[(size_t)sga[mt][1] * H + col];
                }
        }

        // ---- layer2 (fp16): h1 @ W2 ----
        #pragma unroll
        for (int ks = 0; ks < 8; ++ks) {
            uint32_t A[2][4], B[2][4];
            #pragma unroll
            for (int mt = 0; mt < 2; ++mt) {
                uint32_t ad = sb + H1_OFF + (uint32_t)(arow0 + mt * 16) * 256u
                            + ((((ks << 1) + hA) ^ subA) << 4);
                ldsm4(A[mt][0], A[mt][1], A[mt][2], A[mt][3], ad);
            }
            #pragma unroll
            for (int p = 0; p < 2; ++p) {
                uint32_t bd = sb + W2_OFF + (uint32_t)(brow0 + p * 16) * 256u
                            + ((((ks << 1) + hB) ^ subB) << 4);
                ldsm4(B[p][0], B[p][1], B[p][2], B[p][3], bd);
            }
            #pragma unroll
            for (int mt = 0; mt < 2; ++mt) {
                mma16(acc[mt][0], A[mt], B[0][0], B[0][1]);
                mma16(acc[mt][1], A[mt], B[0][2], B[0][3]);
                mma16(acc[mt][2], A[mt], B[1][0], B[1][1]);
                mma16(acc[mt][3], A[mt], B[1][2], B[1][3]);
            }
        }

        // STS next-tile X (consumed after next barrier (a))
        if (nxt < numTiles) {
            #pragma unroll
            for (int i = 0; i < 4; ++i) {
                const int u = xu0 + i;
                uint4 v;
                v.x = pack_f16x2(pa[i].x, pa[i].y); v.y = pack_f16x2(pa[i].z, pa[i].w);
                v.z = pack_f16x2(pb[i].x, pb[i].y); v.w = pack_f16x2(pb[i].z, pb[i].w);
                *(uint4*)(smem + X_OFF + (uint32_t)xrow * 256u
                          + ((((uint32_t)u) ^ ((uint32_t)xrow & 7)) << 4)) = v;
            }
        }

        // ---- epilogue2: +b2, relu, STG ----
        #pragma unroll
        for (int mt = 0; mt < 2; ++mt) {
            const int ra = base + wr * 32 + mt * 16 + gr;
            #pragma unroll
            for (int nt = 0; nt < 4; ++nt) {
                const int col = wc * 32 + nt * 8 + 2 * tg;
                const float bx = b2s[col], by = b2s[col + 1];
                float2 v;
                v.x = fmaxf(acc[mt][nt][0] + bx, 0.0f);
                v.y = fmaxf(acc[mt][nt][1] + by, 0.0f);
                *(float2*)&n_out[(size_t)ra * H + col] = v;
                v.x = fmaxf(acc[mt][nt][2] + bx, 0.0f);
                v.y = fmaxf(acc[mt][nt][3] + by, 0.0f);
                *(float2*)&n_out[(size_t)(ra + 8) * H + col] = v;
            }
        }
    }
}

extern "C" void kernel_launch(void* const* d_in, const int* in_sizes, int n_in,
                              void* d_out, int out_size) {
    const float* uset  = (const float*)d_in[0];   // [G, H]
    const float* unode = (const float*)d_in[1];   // [N, H]
    const int*   seg   = (const int*)d_in[2];     // [N]
    const float* Ws1   = (const float*)d_in[3];
    const float* bs1   = (const float*)d_in[4];
    const float* Ws2   = (const float*)d_in[5];
    const float* bs2   = (const float*)d_in[6];
    const float* Wn1   = (const float*)d_in[7];
    const float* bn1   = (const float*)d_in[8];
    const float* Wn2   = (const float*)d_in[9];
    const float* bn2   = (const float*)d_in[10];

    const int G = in_sizes[0] / H;
    const int N = in_sizes[1] / H;

    float* s_out = (float*)d_out;                  // [G, H]
    float* n_out = (float*)d_out + (size_t)G * H;  // [N, H]

    zero_agg_kernel<<<(G * H + 255) / 256, 256>>>(G * H);
    seg_sum_kernel<<<N / 512, 256>>>((const float4*)unode, seg);
    set_mlp_c_kernel<<<G / 8, 128>>>(uset, Ws1, bs1, Ws2, bs2, Wn1, bn1, s_out);

    static int smem_set = 0;
    if (!smem_set) {
        cudaFuncSetAttribute(fused_node_mlp,
                             cudaFuncAttributeMaxDynamicSharedMemorySize, F_SMEM);
        smem_set = 1;
    }
    const int numTiles = N / 64;                   // 64-row tiles
    int grid = 2 * 148;
    if (grid > numTiles) grid = numTiles;
    fused_node_mlp<<<grid, 256, F_SMEM>>>(unode, seg, Wn1, Wn2, bn2, n_out, numTiles);
}

// round 11
// speedup vs baseline: 1.1968x; 1.1968x over previous
#include <cuda_runtime.h>
#include <cuda_fp16.h>
#include <cstdint>

#define H 128

// Scratch: segment sums [G,H]; c[g] = s[g] @ W1[128:256] + b1  (fp32).
__device__ float g_agg[4096 * 128];
__device__ float g_c[4096 * 128];

// ============================================================================
// Base-target PTX helpers
// ============================================================================
__device__ __forceinline__ uint32_t f2tf32(float f) {
    uint32_t u;
    asm("cvt.rna.tf32.f32 %0, %1;" : "=r"(u) : "f"(f));
    return u;
}
__device__ __forceinline__ uint32_t pack_f16x2(float lo, float hi) {
    uint32_t u;
    asm("cvt.rn.f16x2.f32 %0, %1, %2;" : "=r"(u) : "f"(hi), "f"(lo));
    return u;
}
__device__ __forceinline__ uint32_t smem_u32_of(const void* p) {
    uint32_t a;
    asm("{ .reg .u64 t; cvta.to.shared.u64 t, %1; cvt.u32.u64 %0, t; }"
        : "=r"(a) : "l"(p));
    return a;
}
__device__ __forceinline__ void mma8(float* d, const uint32_t* a,
                                     uint32_t b0, uint32_t b1) {
    asm volatile(
        "mma.sync.aligned.m16n8k8.row.col.f32.tf32.tf32.f32 "
        "{%0,%1,%2,%3},{%4,%5,%6,%7},{%8,%9},{%0,%1,%2,%3};"
        : "+f"(d[0]), "+f"(d[1]), "+f"(d[2]), "+f"(d[3])
        : "r"(a[0]), "r"(a[1]), "r"(a[2]), "r"(a[3]), "r"(b0), "r"(b1));
}
__device__ __forceinline__ void mma16(float* d, const uint32_t* a,
                                      uint32_t b0, uint32_t b1) {
    asm volatile(
        "mma.sync.aligned.m16n8k16.row.col.f32.f16.f16.f32 "
        "{%0,%1,%2,%3},{%4,%5,%6,%7},{%8,%9},{%0,%1,%2,%3};"
        : "+f"(d[0]), "+f"(d[1]), "+f"(d[2]), "+f"(d[3])
        : "r"(a[0]), "r"(a[1]), "r"(a[2]), "r"(a[3]), "r"(b0), "r"(b1));
}
__device__ __forceinline__ void ldsm4(uint32_t& r0, uint32_t& r1,
                                      uint32_t& r2, uint32_t& r3, uint32_t addr) {
    asm volatile("ldmatrix.sync.aligned.m8n8.x4.shared.b16 {%0,%1,%2,%3}, [%4];"
                 : "=r"(r0), "=r"(r1), "=r"(r2), "=r"(r3) : "r"(addr));
}
#define CP_ASYNC16(dst, src) \
    asm volatile("cp.async.cg.shared.global [%0], [%1], 16;" :: "r"(dst), "l"(src))
#define CP_COMMIT() asm volatile("cp.async.commit_group;" ::: "memory")
#define CP_WAIT(n)  asm volatile("cp.async.wait_group %0;" :: "n"(n) : "memory")

// ============================================================================
// Small kernels
// ============================================================================
__global__ void zero_agg_kernel(int n) {
    int i = blockIdx.x * blockDim.x + threadIdx.x;
    if (i < n) g_agg[i] = 0.0f;
}

__global__ void seg_sum_kernel(const float4* __restrict__ node4,
                               const int* __restrict__ seg) {
    __shared__ int sseg[512];
    const int base = blockIdx.x * 512;
    const int tid = threadIdx.x;
    for (int i = tid; i < 512; i += 256) sseg[i] = seg[base + i];
    __syncthreads();
    const int c4 = tid & 31, rp = tid >> 5;
    const int r0 = rp * 64;
    float4 acc = make_float4(0.f, 0.f, 0.f, 0.f);
    int cur = sseg[r0];
    #pragma unroll 4
    for (int i = 0; i < 64; ++i) {
        const int r = r0 + i;
        const int id = sseg[r];
        if (id != cur) {
            float* dst = &g_agg[cur * H + c4 * 4];
            atomicAdd(dst + 0, acc.x); atomicAdd(dst + 1, acc.y);
            atomicAdd(dst + 2, acc.z); atomicAdd(dst + 3, acc.w);
            acc = make_float4(0.f, 0.f, 0.f, 0.f);
            cur = id;
        }
        float4 v = node4[(size_t)(base + r) * 32 + c4];
        acc.x += v.x; acc.y += v.y; acc.z += v.z; acc.w += v.w;
    }
    float* dst = &g_agg[cur * H + c4 * 4];
    atomicAdd(dst + 0, acc.x); atomicAdd(dst + 1, acc.y);
    atomicAdd(dst + 2, acc.z); atomicAdd(dst + 3, acc.w);
}

__global__ void set_mlp_c_kernel(const float* __restrict__ uset,
                                 const float* __restrict__ Ws1,
                                 const float* __restrict__ bs1,
                                 const float* __restrict__ Ws2,
                                 const float* __restrict__ bs2,
                                 const float* __restrict__ W1g,
                                 const float* __restrict__ b1g,
                                 float* __restrict__ s_out) {
    __shared__ float x[8][256];
    __shared__ float h1[8][128];
    __shared__ float sres[8][128];
    const int j = threadIdx.x;
    const int rbase = blockIdx.x * 8;
    for (int idx = j; idx < 8 * 256; idx += 128) {
        int r = idx >> 8, k = idx & 255;
        x[r][k] = (k < 128) ? g_agg[(rbase + r) * H + k]
                            : uset[(size_t)(rbase + r) * H + (k - 128)];
    }
    __syncthreads();
    float acc[8];
    float b1 = bs1[j];
    #pragma unroll
    for (int r = 0; r < 8; ++r) acc[r] = b1;
    for (int k = 0; k < 256; ++k) {
        float w = Ws1[k * H + j];
        #pragma unroll
        for (int r = 0; r < 8; ++r) acc[r] += x[r][k] * w;
    }
    #pragma unroll
    for (int r = 0; r < 8; ++r) h1[r][j] = fmaxf(acc[r], 0.0f);
    __syncthreads();
    float b2 = bs2[j];
    #pragma unroll
    for (int r = 0; r < 8; ++r) acc[r] = b2;
    for (int k = 0; k < 128; ++k) {
        float w = Ws2[k * H + j];
        #pragma unroll
        for (int r = 0; r < 8; ++r) acc[r] += h1[r][k] * w;
    }
    #pragma unroll
    for (int r = 0; r < 8; ++r) {
        float v = fmaxf(acc[r], 0.0f);
        sres[r][j] = v;
        s_out[(size_t)(rbase + r) * H + j] = v;
    }
    __syncthreads();
    float bb = b1g[j];
    #pragma unroll
    for (int r = 0; r < 8; ++r) acc[r] = bb;
    for (int k = 0; k < 128; ++k) {
        float w = W1g[(size_t)(128 + k) * H + j];
        #pragma unroll
        for (int r = 0; r < 8; ++r) acc[r] += sres[r][k] * w;
    }
    #pragma unroll
    for (int r = 0; r < 8; ++r) g_c[(size_t)(rbase + r) * H + j] = acc[r];
}

// ============================================================================
// Fused node MLP (R7 structure + staged c-buffer):
//   layer1 tf32 (X fp32 via cp.async, double-buffered K=64 chunks)
//   epilogue1: + c (staged per-tile in smem, sorted-seg span), relu -> h1 fp16
//   layer2 fp16 m16n8k16: h1 @ W2 + b2, relu -> STG
// ============================================================================
#define W1_OFF   0        // 65536 (tf32)
#define W2_OFF   65536    // 32768 (fp16)
#define BUF0     98304    // 32768 (fp32 X chunk)
#define BUF1     131072   // 32768
#define H1_OFF   163840   // 32768 (fp16)
#define B2S_OFF  196608   // 512
#define SEG_OFF  197120   // 512
#define CB_OFF   197632   // 32 graphs x 132 floats = 16896
#define CB_CAP   32
#define F_SMEM   214528

__global__ void __launch_bounds__(512, 1)
fused_node_mlp(const float* __restrict__ node,
               const int* __restrict__ seg,
               const float* __restrict__ W1g,
               const float* __restrict__ W2g,
               const float* __restrict__ b2g,
               float* __restrict__ n_out,
               int numTiles) {
    extern __shared__ __align__(16) char smem[];
    const uint32_t sb = smem_u32_of(smem);
    float* b2s = (float*)(smem + B2S_OFF);
    int* segs = (int*)(smem + SEG_OFF);
    float* cbuf = (float*)(smem + CB_OFF);

    const int tid = threadIdx.x, lane = tid & 31, wid = tid >> 5;
    const int wr = wid & 3, wc = wid >> 2;
    const int gr = lane >> 2, tg = lane & 3;
    const int ldrow = tid >> 4, ldq = tid & 15;

    // one-time: W1a tf32, W2 fp16, bias
    for (int idx = tid; idx < 128 * 128; idx += 512) {
        int n = idx >> 7, k = idx & 127;
        uint32_t o1 = (uint32_t)n * 512u + ((((uint32_t)k >> 2) ^ (n & 7)) << 4)
                    + ((uint32_t)k & 3) * 4u;
        *(uint32_t*)(smem + W1_OFF + o1) = f2tf32(W1g[(size_t)k * H + n]);
        uint32_t o2 = (uint32_t)n * 256u + ((((uint32_t)k >> 3) ^ (n & 7)) << 4)
                    + ((uint32_t)k & 7) * 2u;
        *(__half*)(smem + W2_OFF + o2) = __float2half_rn(W2g[(size_t)k * H + n]);
    }
    if (tid < 128) b2s[tid] = b2g[tid];

    // ldsm lane constants
    const int subA = lane & 7;
    const int arow0 = wr * 32 + ((lane >> 3) & 1) * 8 + subA;  // + mt*16
    const int hA = lane >> 4;
    const int subB = lane & 7;
    const int brow0 = wc * 32 + ((lane >> 4) & 1) * 8 + subB;  // + p*16
    const int hB = (lane >> 3) & 1;

    const uint32_t dsto = (uint32_t)ldrow * 256u
                        + (((uint32_t)ldq ^ ((uint32_t)ldrow & 7)) << 4);

    // prologue: issue both chunks of first tile
    {
        const int base = blockIdx.x * 128;
        if (blockIdx.x < numTiles) {
            #pragma unroll
            for (int it = 0; it < 4; ++it) {
                int row = ldrow + it * 32;
                CP_ASYNC16(sb + BUF0 + dsto + it * 8192u,
                           &node[(size_t)(base + row) * H + ldq * 4]);
            }
        }
        CP_COMMIT();
        if (blockIdx.x < numTiles) {
            #pragma unroll
            for (int it = 0; it < 4; ++it) {
                int row = ldrow + it * 32;
                CP_ASYNC16(sb + BUF1 + dsto + it * 8192u,
                           &node[(size_t)(base + row) * H + 64 + ldq * 4]);
            }
        }
        CP_COMMIT();
    }

    float acc[2][4][4];

    for (int tile = blockIdx.x; tile < numTiles; tile += gridDim.x) {
        const int base = tile * 128;
        if (tid < 128) segs[tid] = seg[base + tid];
        CP_WAIT(1);
        __syncthreads();   // (a) chunk0 + segs visible; prev h1/cbuf reads done

        // stage this tile's distinct c rows (sorted seg => contiguous span)
        const int g0 = segs[0];
        const int span = segs[127] - g0 + 1;
        if (span <= CB_CAP) {
            for (int idx = tid; idx < span * 128; idx += 512) {
                int gi = idx >> 7, cc = idx & 127;
                cbuf[gi * 132 + cc] = g_c[(size_t)(g0 + gi) * H + cc];
            }
        }

        #pragma unroll
        for (int mt = 0; mt < 2; ++mt)
            #pragma unroll
            for (int nt = 0; nt < 4; ++nt)
                #pragma unroll
                for (int j = 0; j < 4; ++j) acc[mt][nt][j] = 0.0f;

        // ---- layer1 (tf32): chunk0 (BUF0) then chunk1 (BUF1) ----
        #pragma unroll
        for (int c = 0; c < 2; ++c) {
            const uint32_t xb = sb + (c ? BUF1 : BUF0);
            const int kqb = c * 16;
            #pragma unroll
            for (int ks = 0; ks < 8; ++ks) {
                uint32_t A[2][4], B[2][4];
                #pragma unroll
                for (int mt = 0; mt < 2; ++mt) {
                    uint32_t ad = xb + (uint32_t)(arow0 + mt * 16) * 256u
                                + ((((ks << 1) + hA) ^ subA) << 4);
                    ldsm4(A[mt][0], A[mt][1], A[mt][2], A[mt][3], ad);
                }
                #pragma unroll
                for (int p = 0; p < 2; ++p) {
                    uint32_t bd = sb + W1_OFF + (uint32_t)(brow0 + p * 16) * 512u
                                + (((kqb + (ks << 1) + hB) ^ subB) << 4);
                    ldsm4(B[p][0], B[p][1], B[p][2], B[p][3], bd);
                }
                #pragma unroll
                for (int mt = 0; mt < 2; ++mt) {
                    mma8(acc[mt][0], A[mt], B[0][0], B[0][1]);
                    mma8(acc[mt][1], A[mt], B[0][2], B[0][3]);
                    mma8(acc[mt][2], A[mt], B[1][0], B[1][1]);
                    mma8(acc[mt][3], A[mt], B[1][2], B[1][3]);
                }
            }
            if (c == 0) {
                CP_WAIT(0);
                __syncthreads();   // (b) chunk1 ready; cbuf writes visible
            }
        }

        // ---- epilogue1: + c (from cbuf / fallback), relu, fp16 -> h1 ----
        #pragma unroll
        for (int mt = 0; mt < 2; ++mt) {
            const int ra = wr * 32 + mt * 16 + gr;
            const int ia = segs[ra] - g0, ib = segs[ra + 8] - g0;
            #pragma unroll
            for (int nt = 0; nt < 4; ++nt) {
                const int col = wc * 32 + nt * 8 + 2 * tg;
                float2 ca, cb;
                if (span <= CB_CAP) {
                    ca = *(const float2*)&cbuf[ia * 132 + col];
                    cb = *(const float2*)&cbuf[ib * 132 + col];
                } else {
                    ca = *(const float2*)&g_c[(size_t)(g0 + ia) * H + col];
                    cb = *(const float2*)&g_c[(size_t)(g0 + ib) * H + col];
                }
                const uint32_t unit = (uint32_t)(col >> 3);
                uint32_t v01 = pack_f16x2(fmaxf(acc[mt][nt][0] + ca.x, 0.0f),
                                          fmaxf(acc[mt][nt][1] + ca.y, 0.0f));
                *(uint32_t*)(smem + H1_OFF + (uint32_t)ra * 256u
                             + ((unit ^ ((uint32_t)ra & 7)) << 4)
                             + ((uint32_t)col & 7) * 2u) = v01;
                uint32_t v23 = pack_f16x2(fmaxf(acc[mt][nt][2] + cb.x, 0.0f),
                                          fmaxf(acc[mt][nt][3] + cb.y, 0.0f));
                *(uint32_t*)(smem + H1_OFF + (uint32_t)(ra + 8) * 256u
                             + ((unit ^ (((uint32_t)ra + 8) & 7)) << 4)
                             + ((uint32_t)col & 7) * 2u) = v23;
                #pragma unroll
                for (int j = 0; j < 4; ++j) acc[mt][nt][j] = 0.0f;
            }
        }
        __syncthreads();   // (d) h1 visible; BUF0/1 reads done

        // issue next tile chunks (hidden behind layer2)
        const int nxt = tile + gridDim.x;
        if (nxt < numTiles) {
            const int nb = nxt * 128;
            #pragma unroll
            for (int it = 0; it < 4; ++it) {
                int row = ldrow + it * 32;
                CP_ASYNC16(sb + BUF0 + dsto + it * 8192u,
                           &node[(size_t)(nb + row) * H + ldq * 4]);
            }
        }
        CP_COMMIT();
        if (nxt < numTiles) {
            const int nb = nxt * 128;
            #pragma unroll
            for (int it = 0; it < 4; ++it) {
                int row = ldrow + it * 32;
                CP_ASYNC16(sb + BUF1 + dsto + it * 8192u,
                           &node[(size_t)(nb + row) * H + 64 + ldq * 4]);
            }
        }
        CP_COMMIT();

        // ---- layer2 (fp16 m16n8k16): h1 @ W2 ----
        #pragma unroll
        for (int ks = 0; ks < 8; ++ks) {
            uint32_t A[2][4], B[2][4];
            #pragma unroll
            for (int mt = 0; mt < 2; ++mt) {
                uint32_t ad = sb + H1_OFF + (uint32_t)(arow0 + mt * 16) * 256u
                            + ((((ks << 1) + hA) ^ subA) << 4);
                ldsm4(A[mt][0], A[mt][1], A[mt][2], A[mt][3], ad);
            }
            #pragma unroll
            for (int p = 0; p < 2; ++p) {
                uint32_t bd = sb + W2_OFF + (uint32_t)(brow0 + p * 16) * 256u
                            + ((((ks << 1) + hB) ^ subB) << 4);
                ldsm4(B[p][0], B[p][1], B[p][2], B[p][3], bd);
            }
            #pragma unroll
            for (int mt = 0; mt < 2; ++mt) {
                mma16(acc[mt][0], A[mt], B[0][0], B[0][1]);
                mma16(acc[mt][1], A[mt], B[0][2], B[0][3]);
                mma16(acc[mt][2], A[mt], B[1][0], B[1][1]);
                mma16(acc[mt][3], A[mt], B[1][2], B[1][3]);
            }
        }

        // ---- epilogue2: +b2, relu, STG ----
        #pragma unroll
        for (int mt = 0; mt < 2; ++mt) {
            const int ra = base + wr * 32 + mt * 16 + gr;
            #pragma unroll
            for (int nt = 0; nt < 4; ++nt) {
                const int col = wc * 32 + nt * 8 + 2 * tg;
                const float bx = b2s[col], by = b2s[col + 1];
                float2 v;
                v.x = fmaxf(acc[mt][nt][0] + bx, 0.0f);
                v.y = fmaxf(acc[mt][nt][1] + by, 0.0f);
                *(float2*)&n_out[(size_t)ra * H + col] = v;
                v.x = fmaxf(acc[mt][nt][2] + bx, 0.0f);
                v.y = fmaxf(acc[mt][nt][3] + by, 0.0f);
                *(float2*)&n_out[(size_t)(ra + 8) * H + col] = v;
            }
        }
    }
}

extern "C" void kernel_launch(void* const* d_in, const int* in_sizes, int n_in,
                              void* d_out, int out_size) {
    const float* uset  = (const float*)d_in[0];   // [G, H]
    const float* unode = (const float*)d_in[1];   // [N, H]
    const int*   seg   = (const int*)d_in[2];     // [N]
    const float* Ws1   = (const float*)d_in[3];
    const float* bs1   = (const float*)d_in[4];
    const float* Ws2   = (const float*)d_in[5];
    const float* bs2   = (const float*)d_in[6];
    const float* Wn1   = (const float*)d_in[7];
    const float* bn1   = (const float*)d_in[8];
    const float* Wn2   = (const float*)d_in[9];
    const float* bn2   = (const float*)d_in[10];

    const int G = in_sizes[0] / H;
    const int N = in_sizes[1] / H;

    float* s_out = (float*)d_out;                  // [G, H]
    float* n_out = (float*)d_out + (size_t)G * H;  // [N, H]

    zero_agg_kernel<<<(G * H + 255) / 256, 256>>>(G * H);
    seg_sum_kernel<<<N / 512, 256>>>((const float4*)unode, seg);
    set_mlp_c_kernel<<<G / 8, 128>>>(uset, Ws1, bs1, Ws2, bs2, Wn1, bn1, s_out);

    static int smem_set = 0;
    if (!smem_set) {
        cudaFuncSetAttribute(fused_node_mlp,
                             cudaFuncAttributeMaxDynamicSharedMemorySize, F_SMEM);
        smem_set = 1;
    }
    const int numTiles = N / 128;
    const int grid = numTiles < 148 ? numTiles : 148;
    fused_node_mlp<<<grid, 512, F_SMEM>>>(unode, seg, Wn1, Wn2, bn2, n_out, numTiles);
}

// round 12
// speedup vs baseline: 1.2149x; 1.0151x over previous
#include <cuda_runtime.h>
#include <cuda_fp16.h>
#include <cstdint>

#define H 128

// Scratch: segment sums [G,H]; c[g] = s[g] @ W1[128:256] + b1  (fp32).
__device__ float g_agg[4096 * 128];
__device__ float g_c[4096 * 128];

// ============================================================================
// Base-target PTX helpers
// ============================================================================
__device__ __forceinline__ uint32_t f2tf32(float f) {
    uint32_t u;
    asm("cvt.rna.tf32.f32 %0, %1;" : "=r"(u) : "f"(f));
    return u;
}
__device__ __forceinline__ uint32_t pack_f16x2(float lo, float hi) {
    uint32_t u;
    asm("cvt.rn.f16x2.f32 %0, %1, %2;" : "=r"(u) : "f"(hi), "f"(lo));
    return u;
}
__device__ __forceinline__ uint32_t smem_u32_of(const void* p) {
    uint32_t a;
    asm("{ .reg .u64 t; cvta.to.shared.u64 t, %1; cvt.u32.u64 %0, t; }"
        : "=r"(a) : "l"(p));
    return a;
}
__device__ __forceinline__ void mma8(float* d, const uint32_t* a,
                                     uint32_t b0, uint32_t b1) {
    asm volatile(
        "mma.sync.aligned.m16n8k8.row.col.f32.tf32.tf32.f32 "
        "{%0,%1,%2,%3},{%4,%5,%6,%7},{%8,%9},{%0,%1,%2,%3};"
        : "+f"(d[0]), "+f"(d[1]), "+f"(d[2]), "+f"(d[3])
        : "r"(a[0]), "r"(a[1]), "r"(a[2]), "r"(a[3]), "r"(b0), "r"(b1));
}
__device__ __forceinline__ void mma16(float* d, const uint32_t* a,
                                      uint32_t b0, uint32_t b1) {
    asm volatile(
        "mma.sync.aligned.m16n8k16.row.col.f32.f16.f16.f32 "
        "{%0,%1,%2,%3},{%4,%5,%6,%7},{%8,%9},{%0,%1,%2,%3};"
        : "+f"(d[0]), "+f"(d[1]), "+f"(d[2]), "+f"(d[3])
        : "r"(a[0]), "r"(a[1]), "r"(a[2]), "r"(a[3]), "r"(b0), "r"(b1));
}
__device__ __forceinline__ void ldsm4(uint32_t& r0, uint32_t& r1,
                                      uint32_t& r2, uint32_t& r3, uint32_t addr) {
    asm volatile("ldmatrix.sync.aligned.m8n8.x4.shared.b16 {%0,%1,%2,%3}, [%4];"
                 : "=r"(r0), "=r"(r1), "=r"(r2), "=r"(r3) : "r"(addr));
}
#define CP_ASYNC16(dst, src) \
    asm volatile("cp.async.cg.shared.global [%0], [%1], 16;" :: "r"(dst), "l"(src))
#define CP_COMMIT() asm volatile("cp.async.commit_group;" ::: "memory")
#define CP_WAIT(n)  asm volatile("cp.async.wait_group %0;" :: "n"(n) : "memory")

// ============================================================================
// Small kernels
// ============================================================================
__global__ void zero_agg_kernel(int n) {
    int i = blockIdx.x * blockDim.x + threadIdx.x;
    if (i < n) g_agg[i] = 0.0f;
}

__global__ void seg_sum_kernel(const float4* __restrict__ node4,
                               const int* __restrict__ seg) {
    __shared__ int sseg[512];
    const int base = blockIdx.x * 512;
    const int tid = threadIdx.x;
    for (int i = tid; i < 512; i += 256) sseg[i] = seg[base + i];
    __syncthreads();
    const int c4 = tid & 31, rp = tid >> 5;
    const int r0 = rp * 64;
    float4 acc = make_float4(0.f, 0.f, 0.f, 0.f);
    int cur = sseg[r0];
    #pragma unroll 8
    for (int i = 0; i < 64; ++i) {
        const int r = r0 + i;
        const int id = sseg[r];
        if (id != cur) {
            float* dst = &g_agg[cur * H + c4 * 4];
            atomicAdd(dst + 0, acc.x); atomicAdd(dst + 1, acc.y);
            atomicAdd(dst + 2, acc.z); atomicAdd(dst + 3, acc.w);
            acc = make_float4(0.f, 0.f, 0.f, 0.f);
            cur = id;
        }
        float4 v = node4[(size_t)(base + r) * 32 + c4];
        acc.x += v.x; acc.y += v.y; acc.z += v.z; acc.w += v.w;
    }
    float* dst = &g_agg[cur * H + c4 * 4];
    atomicAdd(dst + 0, acc.x); atomicAdd(dst + 1, acc.y);
    atomicAdd(dst + 2, acc.z); atomicAdd(dst + 3, acc.w);
}

// set MLP + c[g]; float4 k-stepping for dense FFMA issue mix.
__global__ void set_mlp_c_kernel(const float* __restrict__ uset,
                                 const float* __restrict__ Ws1,
                                 const float* __restrict__ bs1,
                                 const float* __restrict__ Ws2,
                                 const float* __restrict__ bs2,
                                 const float* __restrict__ W1g,
                                 const float* __restrict__ b1g,
                                 float* __restrict__ s_out) {
    __shared__ __align__(16) float x[8][256];
    __shared__ __align__(16) float h1[8][128];
    __shared__ __align__(16) float sres[8][128];
    const int j = threadIdx.x;
    const int rbase = blockIdx.x * 8;
    for (int idx = j; idx < 8 * 256; idx += 128) {
        int r = idx >> 8, k = idx & 255;
        x[r][k] = (k < 128) ? g_agg[(rbase + r) * H + k]
                            : uset[(size_t)(rbase + r) * H + (k - 128)];
    }
    __syncthreads();
    float acc[8];
    float b1 = bs1[j];
    #pragma unroll
    for (int r = 0; r < 8; ++r) acc[r] = b1;
    #pragma unroll 4
    for (int k4 = 0; k4 < 64; ++k4) {
        const int k = k4 * 4;
        const float w0 = Ws1[(k + 0) * H + j];
        const float w1 = Ws1[(k + 1) * H + j];
        const float w2 = Ws1[(k + 2) * H + j];
        const float w3 = Ws1[(k + 3) * H + j];
        #pragma unroll
        for (int r = 0; r < 8; ++r) {
            float4 xv = *(const float4*)&x[r][k];
            acc[r] += xv.x * w0 + xv.y * w1 + xv.z * w2 + xv.w * w3;
        }
    }
    #pragma unroll
    for (int r = 0; r < 8; ++r) h1[r][j] = fmaxf(acc[r], 0.0f);
    __syncthreads();
    float b2 = bs2[j];
    #pragma unroll
    for (int r = 0; r < 8; ++r) acc[r] = b2;
    #pragma unroll 4
    for (int k4 = 0; k4 < 32; ++k4) {
        const int k = k4 * 4;
        const float w0 = Ws2[(k + 0) * H + j];
        const float w1 = Ws2[(k + 1) * H + j];
        const float w2 = Ws2[(k + 2) * H + j];
        const float w3 = Ws2[(k + 3) * H + j];
        #pragma unroll
        for (int r = 0; r < 8; ++r) {
            float4 xv = *(const float4*)&h1[r][k];
            acc[r] += xv.x * w0 + xv.y * w1 + xv.z * w2 + xv.w * w3;
        }
    }
    #pragma unroll
    for (int r = 0; r < 8; ++r) {
        float v = fmaxf(acc[r], 0.0f);
        sres[r][j] = v;
        s_out[(size_t)(rbase + r) * H + j] = v;
    }
    __syncthreads();
    float bb = b1g[j];
    #pragma unroll
    for (int r = 0; r < 8; ++r) acc[r] = bb;
    #pragma unroll 4
    for (int k4 = 0; k4 < 32; ++k4) {
        const int k = k4 * 4;
        const float w0 = W1g[(size_t)(128 + k + 0) * H + j];
        const float w1 = W1g[(size_t)(128 + k + 1) * H + j];
        const float w2 = W1g[(size_t)(128 + k + 2) * H + j];
        const float w3 = W1g[(size_t)(128 + k + 3) * H + j];
        #pragma unroll
        for (int r = 0; r < 8; ++r) {
            float4 xv = *(const float4*)&sres[r][k];
            acc[r] += xv.x * w0 + xv.y * w1 + xv.z * w2 + xv.w * w3;
        }
    }
    #pragma unroll
    for (int r = 0; r < 8; ++r) g_c[(size_t)(rbase + r) * H + j] = acc[r];
}

// ============================================================================
// Fused node MLP (unchanged R11 WIN config):
//   layer1 tf32 (X fp32 via cp.async, double-buffered K=64 chunks)
//   epilogue1: + c (staged per-tile c-buffer, sorted-seg span), relu -> h1 fp16
//   layer2 fp16 m16n8k16: h1 @ W2 + b2, relu -> STG
// ============================================================================
#define W1_OFF   0        // 65536 (tf32)
#define W2_OFF   65536    // 32768 (fp16)
#define BUF0     98304    // 32768 (fp32 X chunk)
#define BUF1     131072   // 32768
#define H1_OFF   163840   // 32768 (fp16)
#define B2S_OFF  196608   // 512
#define SEG_OFF  197120   // 512
#define CB_OFF   197632   // 32 graphs x 132 floats = 16896
#define CB_CAP   32
#define F_SMEM   214528

__global__ void __launch_bounds__(512, 1)
fused_node_mlp(const float* __restrict__ node,
               const int* __restrict__ seg,
               const float* __restrict__ W1g,
               const float* __restrict__ W2g,
               const float* __restrict__ b2g,
               float* __restrict__ n_out,
               int numTiles) {
    extern __shared__ __align__(16) char smem[];
    const uint32_t sb = smem_u32_of(smem);
    float* b2s = (float*)(smem + B2S_OFF);
    int* segs = (int*)(smem + SEG_OFF);
    float* cbuf = (float*)(smem + CB_OFF);

    const int tid = threadIdx.x, lane = tid & 31, wid = tid >> 5;
    const int wr = wid & 3, wc = wid >> 2;
    const int gr = lane >> 2, tg = lane & 3;
    const int ldrow = tid >> 4, ldq = tid & 15;

    // one-time: W1a tf32, W2 fp16, bias
    for (int idx = tid; idx < 128 * 128; idx += 512) {
        int n = idx >> 7, k = idx & 127;
        uint32_t o1 = (uint32_t)n * 512u + ((((uint32_t)k >> 2) ^ (n & 7)) << 4)
                    + ((uint32_t)k & 3) * 4u;
        *(uint32_t*)(smem + W1_OFF + o1) = f2tf32(W1g[(size_t)k * H + n]);
        uint32_t o2 = (uint32_t)n * 256u + ((((uint32_t)k >> 3) ^ (n & 7)) << 4)
                    + ((uint32_t)k & 7) * 2u;
        *(__half*)(smem + W2_OFF + o2) = __float2half_rn(W2g[(size_t)k * H + n]);
    }
    if (tid < 128) b2s[tid] = b2g[tid];

    // ldsm lane constants
    const int subA = lane & 7;
    const int arow0 = wr * 32 + ((lane >> 3) & 1) * 8 + subA;  // + mt*16
    const int hA = lane >> 4;
    const int subB = lane & 7;
    const int brow0 = wc * 32 + ((lane >> 4) & 1) * 8 + subB;  // + p*16
    const int hB = (lane >> 3) & 1;

    const uint32_t dsto = (uint32_t)ldrow * 256u
                        + (((uint32_t)ldq ^ ((uint32_t)ldrow & 7)) << 4);

    // prologue: issue both chunks of first tile
    {
        const int base = blockIdx.x * 128;
        if (blockIdx.x < numTiles) {
            #pragma unroll
            for (int it = 0; it < 4; ++it) {
                int row = ldrow + it * 32;
                CP_ASYNC16(sb + BUF0 + dsto + it * 8192u,
                           &node[(size_t)(base + row) * H + ldq * 4]);
            }
        }
        CP_COMMIT();
        if (blockIdx.x < numTiles) {
            #pragma unroll
            for (int it = 0; it < 4; ++it) {
                int row = ldrow + it * 32;
                CP_ASYNC16(sb + BUF1 + dsto + it * 8192u,
                           &node[(size_t)(base + row) * H + 64 + ldq * 4]);
            }
        }
        CP_COMMIT();
    }

    float acc[2][4][4];

    for (int tile = blockIdx.x; tile < numTiles; tile += gridDim.x) {
        const int base = tile * 128;
        if (tid < 128) segs[tid] = seg[base + tid];
        CP_WAIT(1);
        __syncthreads();   // (a) chunk0 + segs visible; prev h1/cbuf reads done

        // stage this tile's distinct c rows (sorted seg => contiguous span)
        const int g0 = segs[0];
        const int span = segs[127] - g0 + 1;
        if (span <= CB_CAP) {
            for (int idx = tid; idx < span * 128; idx += 512) {
                int gi = idx >> 7, cc = idx & 127;
                cbuf[gi * 132 + cc] = g_c[(size_t)(g0 + gi) * H + cc];
            }
        }

        #pragma unroll
        for (int mt = 0; mt < 2; ++mt)
            #pragma unroll
            for (int nt = 0; nt < 4; ++nt)
                #pragma unroll
                for (int j = 0; j < 4; ++j) acc[mt][nt][j] = 0.0f;

        // ---- layer1 (tf32): chunk0 (BUF0) then chunk1 (BUF1) ----
        #pragma unroll
        for (int c = 0; c < 2; ++c) {
            const uint32_t xb = sb + (c ? BUF1 : BUF0);
            const int kqb = c * 16;
            #pragma unroll
            for (int ks = 0; ks < 8; ++ks) {
                uint32_t A[2][4], B[2][4];
                #pragma unroll
                for (int mt = 0; mt < 2; ++mt) {
                    uint32_t ad = xb + (uint32_t)(arow0 + mt * 16) * 256u
                                + ((((ks << 1) + hA) ^ subA) << 4);
                    ldsm4(A[mt][0], A[mt][1], A[mt][2], A[mt][3], ad);
                }
                #pragma unroll
                for (int p = 0; p < 2; ++p) {
                    uint32_t bd = sb + W1_OFF + (uint32_t)(brow0 + p * 16) * 512u
                                + (((kqb + (ks << 1) + hB) ^ subB) << 4);
                    ldsm4(B[p][0], B[p][1], B[p][2], B[p][3], bd);
                }
                #pragma unroll
                for (int mt = 0; mt < 2; ++mt) {
                    mma8(acc[mt][0], A[mt], B[0][0], B[0][1]);
                    mma8(acc[mt][1], A[mt], B[0][2], B[0][3]);
                    mma8(acc[mt][2], A[mt], B[1][0], B[1][1]);
                    mma8(acc[mt][3], A[mt], B[1][2], B[1][3]);
                }
            }
            if (c == 0) {
                CP_WAIT(0);
                __syncthreads();   // (b) chunk1 ready; cbuf writes visible
            }
        }

        // ---- epilogue1: + c (from cbuf / fallback), relu, fp16 -> h1 ----
        #pragma unroll
        for (int mt = 0; mt < 2; ++mt) {
            const int ra = wr * 32 + mt * 16 + gr;
            const int ia = segs[ra] - g0, ib = segs[ra + 8] - g0;
            #pragma unroll
            for (int nt = 0; nt < 4; ++nt) {
                const int col = wc * 32 + nt * 8 + 2 * tg;
                float2 ca, cb;
                if (span <= CB_CAP) {
                    ca = *(const float2*)&cbuf[ia * 132 + col];
                    cb = *(const float2*)&cbuf[ib * 132 + col];
                } else {
                    ca = *(const float2*)&g_c[(size_t)(g0 + ia) * H + col];
                    cb = *(const float2*)&g_c[(size_t)(g0 + ib) * H + col];
                }
                const uint32_t unit = (uint32_t)(col >> 3);
                uint32_t v01 = pack_f16x2(fmaxf(acc[mt][nt][0] + ca.x, 0.0f),
                                          fmaxf(acc[mt][nt][1] + ca.y, 0.0f));
                *(uint32_t*)(smem + H1_OFF + (uint32_t)ra * 256u
                             + ((unit ^ ((uint32_t)ra & 7)) << 4)
                             + ((uint32_t)col & 7) * 2u) = v01;
                uint32_t v23 = pack_f16x2(fmaxf(acc[mt][nt][2] + cb.x, 0.0f),
                                          fmaxf(acc[mt][nt][3] + cb.y, 0.0f));
                *(uint32_t*)(smem + H1_OFF + (uint32_t)(ra + 8) * 256u
                             + ((unit ^ (((uint32_t)ra + 8) & 7)) << 4)
                             + ((uint32_t)col & 7) * 2u) = v23;
                #pragma unroll
                for (int j = 0; j < 4; ++j) acc[mt][nt][j] = 0.0f;
            }
        }
        __syncthreads();   // (d) h1 visible; BUF0/1 reads done

        // issue next tile chunks (hidden behind layer2)
        const int nxt = tile + gridDim.x;
        if (nxt < numTiles) {
            const int nb = nxt * 128;
            #pragma unroll
            for (int it = 0; it < 4; ++it) {
                int row = ldrow + it * 32;
                CP_ASYNC16(sb + BUF0 + dsto + it * 8192u,
                           &node[(size_t)(nb + row) * H + ldq * 4]);
            }
        }
        CP_COMMIT();
        if (nxt < numTiles) {
            const int nb = nxt * 128;
            #pragma unroll
            for (int it = 0; it < 4; ++it) {
                int row = ldrow + it * 32;
                CP_ASYNC16(sb + BUF1 + dsto + it * 8192u,
                           &node[(size_t)(nb + row) * H + 64 + ldq * 4]);
            }
        }
        CP_COMMIT();

        // ---- layer2 (fp16 m16n8k16): h1 @ W2 ----
        #pragma unroll
        for (int ks = 0; ks < 8; ++ks) {
            uint32_t A[2][4], B[2][4];
            #pragma unroll
            for (int mt = 0; mt < 2; ++mt) {
                uint32_t ad = sb + H1_OFF + (uint32_t)(arow0 + mt * 16) * 256u
                            + ((((ks << 1) + hA) ^ subA) << 4);
                ldsm4(A[mt][0], A[mt][1], A[mt][2], A[mt][3], ad);
            }
            #pragma unroll
            for (int p = 0; p < 2; ++p) {
                uint32_t bd = sb + W2_OFF + (uint32_t)(brow0 + p * 16) * 256u
                            + ((((ks << 1) + hB) ^ subB) << 4);
                ldsm4(B[p][0], B[p][1], B[p][2], B[p][3], bd);
            }
            #pragma unroll
            for (int mt = 0; mt < 2; ++mt) {
                mma16(acc[mt][0], A[mt], B[0][0], B[0][1]);
                mma16(acc[mt][1], A[mt], B[0][2], B[0][3]);
                mma16(acc[mt][2], A[mt], B[1][0], B[1][1]);
                mma16(acc[mt][3], A[mt], B[1][2], B[1][3]);
            }
        }

        // ---- epilogue2: +b2, relu, STG ----
        #pragma unroll
        for (int mt = 0; mt < 2; ++mt) {
            const int ra = base + wr * 32 + mt * 16 + gr;
            #pragma unroll
            for (int nt = 0; nt < 4; ++nt) {
                const int col = wc * 32 + nt * 8 + 2 * tg;
                const float bx = b2s[col], by = b2s[col + 1];
                float2 v;
                v.x = fmaxf(acc[mt][nt][0] + bx, 0.0f);
                v.y = fmaxf(acc[mt][nt][1] + by, 0.0f);
                *(float2*)&n_out[(size_t)ra * H + col] = v;
                v.x = fmaxf(acc[mt][nt][2] + bx, 0.0f);
                v.y = fmaxf(acc[mt][nt][3] + by, 0.0f);
                *(float2*)&n_out[(size_t)(ra + 8) * H + col] = v;
            }
        }
    }
}

extern "C" void kernel_launch(void* const* d_in, const int* in_sizes, int n_in,
                              void* d_out, int out_size) {
    const float* uset  = (const float*)d_in[0];   // [G, H]
    const float* unode = (const float*)d_in[1];   // [N, H]
    const int*   seg   = (const int*)d_in[2];     // [N]
    const float* Ws1   = (const float*)d_in[3];
    const float* bs1   = (const float*)d_in[4];
    const float* Ws2   = (const float*)d_in[5];
    const float* bs2   = (const float*)d_in[6];
    const float* Wn1   = (const float*)d_in[7];
    const float* bn1   = (const float*)d_in[8];
    const float* Wn2   = (const float*)d_in[9];
    const float* bn2   = (const float*)d_in[10];

    const int G = in_sizes[0] / H;
    const int N = in_sizes[1] / H;

    float* s_out = (float*)d_out;                  // [G, H]
    float* n_out = (float*)d_out + (size_t)G * H;  // [N, H]

    zero_agg_kernel<<<(G * H + 255) / 256, 256>>>(G * H);
    seg_sum_kernel<<<N / 512, 256>>>((const float4*)unode, seg);
    set_mlp_c_kernel<<<G / 8, 128>>>(uset, Ws1, bs1, Ws2, bs2, Wn1, bn1, s_out);

    static int smem_set = 0;
    if (!smem_set) {
        cudaFuncSetAttribute(fused_node_mlp,
                             cudaFuncAttributeMaxDynamicSharedMemorySize, F_SMEM);
        smem_set = 1;
    }
    const int numTiles = N / 128;
    const int grid = numTiles < 148 ? numTiles : 148;
    fused_node_mlp<<<grid, 512, F_SMEM>>>(unode, seg, Wn1, Wn2, bn2, n_out, numTiles);
}